// round 4
// baseline (speedup 1.0000x reference)
#include <cuda_runtime.h>
#include <math.h>

namespace {

constexpr int P      = 13;
constexpr int NS     = 1 << P;     // 8192 amplitudes
constexpr int NPAIR  = NS >> 1;    // 4096 pairs per gate
constexpr int TPB    = 512;
constexpr int NSAMP  = 256;        // B*T
constexpr int D      = 64;
constexpr int NWARP  = TPB / 32;

struct c32 { float x, y; };

__device__ __forceinline__ c32 cmul(c32 a, c32 b) {
    return { fmaf(a.x, b.x, -a.y * b.y), fmaf(a.x, b.y, a.y * b.x) };
}
__device__ __forceinline__ c32 cadd(c32 a, c32 b) { return { a.x + b.x, a.y + b.y }; }

struct mat2 { c32 m[2][2]; };

__device__ __forceinline__ mat2 mmul(const mat2& A, const mat2& B) {
    mat2 C;
#pragma unroll
    for (int i = 0; i < 2; i++)
#pragma unroll
        for (int j = 0; j < 2; j++)
            C.m[i][j] = cadd(cmul(A.m[i][0], B.m[0][j]), cmul(A.m[i][1], B.m[1][j]));
    return C;
}

__device__ __forceinline__ mat2 rx_m(float th) {
    float s, c; sincosf(0.5f * th, &s, &c);
    mat2 U;
    U.m[0][0] = { c, 0.f };  U.m[0][1] = { 0.f, -s };
    U.m[1][0] = { 0.f, -s }; U.m[1][1] = { c, 0.f };
    return U;
}
__device__ __forceinline__ mat2 ry_m(float th) {
    float s, c; sincosf(0.5f * th, &s, &c);
    mat2 U;
    U.m[0][0] = { c, 0.f }; U.m[0][1] = { -s, 0.f };
    U.m[1][0] = { s, 0.f }; U.m[1][1] = { c, 0.f };
    return U;
}
__device__ __forceinline__ mat2 rz_m(float th) {
    float s, c; sincosf(0.5f * th, &s, &c);
    mat2 U;
    U.m[0][0] = { c, -s };   U.m[0][1] = { 0.f, 0.f };
    U.m[1][0] = { 0.f, 0.f }; U.m[1][1] = { c, s };
    return U;
}

// One CNOT of the ring: control wire i (bit P-1-i), target wire (i+1)%P.
// As an index gather map: new[y] = old[g(y)], g(y) = y ^ (ctrl(y) ? tgtbit : 0).
__device__ __forceinline__ int g_cnot(int i, int x) {
    int cb = P - 1 - i;
    int tb = P - 1 - ((i + 1) % P);
    return ((x >> cb) & 1) ? (x ^ (1 << tb)) : x;
}
// Composed gather of the full ring (gates applied i=0..P-1):
// state_after[y] = state_before[G(y)],  G = g_0 ∘ g_1 ∘ ... ∘ g_{P-1}
__device__ __forceinline__ int Gmap(int y) {
    for (int i = P - 1; i >= 0; --i) y = g_cnot(i, y);
    return y;
}
__device__ __forceinline__ int Ginv(int y) {
    for (int i = 0; i < P; i++) y = g_cnot(i, y);   // each g is an involution
    return y;
}

// Dynamic SMEM layout (in floats):
//  s      : [0, 16384)        state, 8192 x c32
//  ang    : [16384, 16424)    39 encoding angles (+1 pad for 8B align of mats)
//  mats   : [16424, 16736)    39 mat2 (8 floats each)
//  m2s    : 13 ints           layer-2 gate XOR masks G(e_w)
//  r2s    : 13 ints           layer-2 orientation row masks (rows of G^-1)
//  rMs    : 13 ints           measurement parity masks (rows of G^-2)
//  wsum   : NWARP*13 floats   per-warp partial <Z_w>
//  expv   : 13 floats
constexpr int SM_S    = 0;
constexpr int SM_ANG  = 16384;
constexpr int SM_MATS = 16424;
constexpr int SM_M2   = SM_MATS + 39 * 8;
constexpr int SM_R2   = SM_M2 + 13;
constexpr int SM_RM   = SM_R2 + 13;
constexpr int SM_WSUM = SM_RM + 13;
constexpr int SM_EXPV = SM_WSUM + NWARP * P;
constexpr int SM_TOT_FLOATS = SM_EXPV + P;
constexpr int SMEM_BYTES = SM_TOT_FLOATS * 4;

__global__ void __launch_bounds__(TPB)
qlc_kernel(const float* __restrict__ h,
           const float* __restrict__ enc_w,
           const float* __restrict__ enc_b,
           const float* __restrict__ qw,
           const float* __restrict__ dec_w,
           const float* __restrict__ alpha,
           float* __restrict__ out)
{
    extern __shared__ float smemf[];
    c32*   s    = (c32*)(smemf + SM_S);
    float* ang  = smemf + SM_ANG;
    mat2*  mats = (mat2*)(smemf + SM_MATS);
    int*   m2s  = (int*)(smemf + SM_M2);
    int*   r2s  = (int*)(smemf + SM_R2);
    int*   rMs  = (int*)(smemf + SM_RM);
    float* wsum = smemf + SM_WSUM;
    float* expv = smemf + SM_EXPV;

    const int n    = blockIdx.x;       // sample index
    const int tid  = threadIdx.x;
    const int wid  = tid >> 5;
    const int lane = tid & 31;

    // ---- init state |0...0> ----
    for (int i = tid; i < NS; i += TPB) {
        s[i].x = (i == 0) ? 1.0f : 0.0f;
        s[i].y = 0.0f;
    }

    // ---- encoding angles: one warp per wire, warp-reduced dot(h_row, enc_w[a]) ----
    if (wid < P) {
        const float* hrow = h + (n * P + wid) * D;
        float h0 = hrow[lane], h1 = hrow[lane + 32];
#pragma unroll
        for (int a = 0; a < 3; a++) {
            float v = h0 * enc_w[a * D + lane] + h1 * enc_w[a * D + lane + 32];
#pragma unroll
            for (int off = 16; off; off >>= 1)
                v += __shfl_xor_sync(0xffffffffu, v, off);
            if (lane == 0) ang[wid * 3 + a] = v + enc_b[a];
        }
    }
    __syncthreads();

    // ---- per-CTA: fused gate matrices + GF(2) masks (cheap, one-shot) ----
    if (tid < P) {
        const int w = tid;
        m2s[w] = Gmap(1 << (P - 1 - w));
        int r = 0, rm = 0;
        for (int p = 0; p < P; p++) {
            int gi  = Ginv(1 << p);
            int gi2 = Ginv(gi);
            r  |= ((gi  >> (P - 1 - w)) & 1) << p;
            rm |= ((gi2 >> (P - 1 - w)) & 1) << p;
        }
        r2s[w] = r;
        rMs[w] = rm;
        // encoding: apply RX then RY then RZ  =>  U = RZ * RY * RX
        mats[w] = mmul(rz_m(ang[w * 3 + 2]), mmul(ry_m(ang[w * 3 + 1]), rx_m(ang[w * 3 + 0])));
    } else if (tid < 3 * P) {
        const int idx = tid - P;           // 0..25
        const int L = idx / P, w = idx % P;
        const float q0 = qw[(L * P + w) * 3 + 0];
        const float q1 = qw[(L * P + w) * 3 + 1];
        const float q2 = qw[(L * P + w) * 3 + 2];
        // apply RY(q0) then RZ(q1) then RY(q2) => U = RY(q2)*RZ(q1)*RY(q0)
        mats[P + idx] = mmul(ry_m(q2), mmul(rz_m(q1), ry_m(q0)));
    }
    __syncthreads();

    // ---- 39 fused gate passes (13 enc + 13 layer1 + 13 layer2-with-masks) ----
    for (int pass = 0; pass < 39; ++pass) {
        const int w = pass % P;
        int m, r;
        if (pass < 26) { m = 1 << (P - 1 - w); r = m; }
        else           { m = m2s[w];          r = r2s[w]; }
        const mat2 U = mats[pass];
        const int b = __ffs(m) - 1;           // pivot bit of the pair mask
        const int lomask = (1 << b) - 1;

        for (int k = tid; k < NPAIR; k += TPB) {
            int x  = ((k & ~lomask) << 1) | (k & lomask);  // insert 0 at pivot bit
            bool flip = (__popc(x & r) & 1) != 0;          // which one is logical-0
            int i0 = flip ? (x ^ m) : x;
            int i1 = i0 ^ m;
            c32 a0 = s[i0], a1 = s[i1];
            c32 n0 = cadd(cmul(U.m[0][0], a0), cmul(U.m[0][1], a1));
            c32 n1 = cadd(cmul(U.m[1][0], a0), cmul(U.m[1][1], a1));
            s[i0] = n0;
            s[i1] = n1;
        }
        __syncthreads();
    }

    // ---- <Z_w> via parity masks of (G^2)^-1 (deterministic reduction) ----
    int rm[P];
#pragma unroll
    for (int w = 0; w < P; w++) rm[w] = rMs[w];

    float acc[P];
#pragma unroll
    for (int w = 0; w < P; w++) acc[w] = 0.0f;

    for (int i = tid; i < NS; i += TPB) {
        c32 a = s[i];
        float pr = a.x * a.x + a.y * a.y;
#pragma unroll
        for (int w = 0; w < P; w++)
            acc[w] += (__popc(i & rm[w]) & 1) ? -pr : pr;
    }
#pragma unroll
    for (int w = 0; w < P; w++) {
        float v = acc[w];
#pragma unroll
        for (int off = 16; off; off >>= 1)
            v += __shfl_xor_sync(0xffffffffu, v, off);
        if (lane == 0) wsum[wid * P + w] = v;
    }
    __syncthreads();
    if (tid < P) {
        float v = 0.0f;
        for (int k = 0; k < NWARP; k++) v += wsum[k * P + tid];
        expv[tid] = v;
    }
    __syncthreads();

    // ---- decode + residual: out = h + alpha * expv[w] * dec_w[d] ----
    const float al = alpha[0];
    const int base = n * P * D;
    for (int e = tid; e < P * D; e += TPB) {
        const int w = e >> 6;      // / D
        const int d = e & 63;      // % D
        out[base + e] = h[base + e] + al * expv[w] * dec_w[d];
    }
}

} // anonymous namespace

extern "C" void kernel_launch(void* const* d_in, const int* in_sizes, int n_in,
                              void* d_out, int out_size)
{
    const float* h     = (const float*)d_in[0];
    const float* enc_w = (const float*)d_in[1];
    const float* enc_b = (const float*)d_in[2];
    const float* qw    = (const float*)d_in[3];
    const float* dec_w = (const float*)d_in[4];
    const float* alpha = (const float*)d_in[5];
    float* out = (float*)d_out;

    cudaFuncSetAttribute(qlc_kernel, cudaFuncAttributeMaxDynamicSharedMemorySize, SMEM_BYTES);
    qlc_kernel<<<NSAMP, TPB, SMEM_BYTES>>>(h, enc_w, enc_b, qw, dec_w, alpha, out);
}

// round 7
// speedup vs baseline: 2.6410x; 2.6410x over previous
#include <cuda_runtime.h>
#include <math.h>

namespace {

constexpr int P     = 13;
constexpr int NS    = 1 << P;      // 8192 amplitudes
constexpr int TPB   = 512;
constexpr int D     = 64;
constexpr int NWARP = TPB / 32;

struct c32 { float x, y; };

__device__ __forceinline__ c32 cmul(c32 a, c32 b) {
    return { fmaf(a.x, b.x, -a.y * b.y), fmaf(a.x, b.y, a.y * b.x) };
}
__device__ __forceinline__ c32 cadd(c32 a, c32 b) { return { a.x + b.x, a.y + b.y }; }

// ---------------- compile-time GF(2) machinery ----------------

__host__ __device__ constexpr int cg_cnot(int i, int x) {
    int cb = P - 1 - i;
    int tb = P - 1 - ((i + 1) % P);
    return ((x >> cb) & 1) ? (x ^ (1 << tb)) : x;
}
__host__ __device__ constexpr int cGmap(int y) {
    for (int i = P - 1; i >= 0; --i) y = cg_cnot(i, y);
    return y;
}
__host__ __device__ constexpr int cGinv(int y) {
    for (int i = 0; i < P; i++) y = cg_cnot(i, y);
    return y;
}
__host__ __device__ constexpr int cpop(int x) { int c = 0; for (int i = 0; i < 16; i++) c += (x >> i) & 1; return c; }
__host__ __device__ constexpr int cctz(int x) { for (int i = 0; i < 16; i++) if ((x >> i) & 1) return i; return -1; }

struct QCData {
    int m2[P];            // layer-2 pair masks  G(e_w)
    int r2[P];            // layer-2 orientation masks (rows of G^-1)
    int rm[P];            // measurement parity masks (rows of G^-2)
    int npos[3][9];       // non-pivot bit positions per batch (ascending)
    int combo[3][16];     // XOR offsets of the 16 coset members
    int lm[3][4];         // local 4-bit pair pattern per gate
    int lml[3][4];        // lowest set bit of lm (canonical selector)
    int lr[3][4];         // local parity pattern per gate
    int rw[3][4];         // full orientation mask per gate (for px)
};

__host__ __device__ constexpr QCData make_qc() {
    QCData q{};
    for (int w = 0; w < P; w++) {
        q.m2[w] = cGmap(1 << (P - 1 - w));
        int r = 0, rm = 0;
        for (int p = 0; p < P; p++) {
            int gi  = cGinv(1 << p);
            int gi2 = cGinv(gi);
            r  |= ((gi  >> (P - 1 - w)) & 1) << p;
            rm |= ((gi2 >> (P - 1 - w)) & 1) << p;
        }
        q.r2[w] = r; q.rm[w] = rm;
    }
    for (int b = 0; b < 3; b++) {
        int f[4] = {}, piv[4] = {};
        for (int i = 0; i < 4; i++) f[i] = q.m2[4 * b + i];
        for (int i = 0; i < 4; i++) {
            for (int j = 0; j < i; j++) if ((f[i] >> piv[j]) & 1) f[i] ^= f[j];
            piv[i] = cctz(f[i]);
            for (int j = 0; j < i; j++) if ((f[j] >> piv[i]) & 1) f[j] ^= f[i];
        }
        int np = 0;
        for (int bit = 0; bit < P; bit++) {
            bool isp = false;
            for (int i = 0; i < 4; i++) if (piv[i] == bit) isp = true;
            if (!isp) q.npos[b][np++] = bit;
        }
        for (int j = 0; j < 16; j++) {
            int c = 0;
            for (int i = 0; i < 4; i++) if ((j >> i) & 1) c ^= f[i];
            q.combo[b][j] = c;
        }
        for (int g = 0; g < 4; g++) {
            int m = q.m2[4 * b + g], r = q.r2[4 * b + g];
            int lm = 0, lr = 0;
            for (int i = 0; i < 4; i++) {
                lm |= ((m >> piv[i]) & 1) << i;
                lr |= (cpop(f[i] & r) & 1) << i;
            }
            q.lm[b][g] = lm;
            q.lml[b][g] = lm & (-lm);
            q.lr[b][g] = lr;
            q.rw[b][g] = r;
        }
    }
    return q;
}

// SMEM bank-conflict swizzle: XOR bits[7:4] into bits[3:0]. Bijection on [0,8192).
__device__ __forceinline__ int sw(int y) { return y ^ ((y >> 4) & 0xF); }

// ---------------- SMEM layout (floats) ----------------
constexpr int SM_S    = 0;                    // 8192 c32 = 16384 floats
constexpr int SM_ANG  = 16384;                // 13*3 (+pad) = 40
constexpr int SM_COLA = 16424;                // 13*2 c32 = 52 floats (8B aligned)
constexpr int SM_MATB = 16476;                // 13*8 = 104 floats (8B aligned)
constexpr int SM_WSUM = 16580;                // NWARP*13 = 208
constexpr int SM_EXPV = 16788;                // 13
constexpr int SMEM_BYTES = (16788 + 13 + 3) * 4;

// Batch of 4 masked gates, fully in registers.
template <int B>
__device__ __forceinline__ void do_batch(c32* __restrict__ s, const float* __restrict__ matB, int tid)
{
    constexpr QCData q = make_qc();
    int x = 0;
#pragma unroll
    for (int i = 0; i < 9; i++) x |= ((tid >> i) & 1) << q.npos[B][i];

    c32 reg[16];
#pragma unroll
    for (int j = 0; j < 16; j++) reg[j] = s[sw(x ^ q.combo[B][j])];

#pragma unroll
    for (int g = 0; g < 4; g++) {
        const int w = 4 * B + g;
        const float* M = matB + w * 8;
        const c32 u00 = { M[0], M[1] }, u01 = { M[2], M[3] };
        const c32 u10 = { M[4], M[5] }, u11 = { M[6], M[7] };
        const int px = __popc(x & q.rw[B][g]) & 1;
#pragma unroll
        for (int j = 0; j < 16; j++) {
            if (j & q.lml[B][g]) continue;               // canonical of each pair (folds)
            const int jp = j ^ q.lm[B][g];               // compile-time partner index
            const int oj = px ^ (cpop(j & q.lr[B][g]) & 1);
            c32 va = reg[j], vb = reg[jp];
            c32 a0 = oj ? vb : va;
            c32 a1 = oj ? va : vb;
            c32 n0 = cadd(cmul(u00, a0), cmul(u01, a1));
            c32 n1 = cadd(cmul(u10, a0), cmul(u11, a1));
            reg[j]  = oj ? n1 : n0;
            reg[jp] = oj ? n0 : n1;
        }
    }
#pragma unroll
    for (int j = 0; j < 16; j++) s[sw(x ^ q.combo[B][j])] = reg[j];
}

__global__ void __launch_bounds__(TPB, 2)
qlc_kernel(const float* __restrict__ h,
           const float* __restrict__ enc_w,
           const float* __restrict__ enc_b,
           const float* __restrict__ qw,
           const float* __restrict__ dec_w,
           const float* __restrict__ alpha,
           float* __restrict__ out)
{
    extern __shared__ float smemf[];
    c32*   s    = (c32*)(smemf + SM_S);
    float* ang  = smemf + SM_ANG;
    c32*   colA = (c32*)(smemf + SM_COLA);   // [13][2] fused (enc+L1) column-0
    float* matB = smemf + SM_MATB;           // [13][8] layer-2 gate matrices
    float* wsum = smemf + SM_WSUM;
    float* expv = smemf + SM_EXPV;

    const int n = blockIdx.x, tid = threadIdx.x, wid = tid >> 5, lane = tid & 31;

    // ---- encoding angles: one warp per wire ----
    if (wid < P) {
        const float* hrow = h + (n * P + wid) * D;
        float h0 = hrow[lane], h1 = hrow[lane + 32];
#pragma unroll
        for (int a = 0; a < 3; a++) {
            float v = h0 * enc_w[a * D + lane] + h1 * enc_w[a * D + lane + 32];
#pragma unroll
            for (int off = 16; off; off >>= 1)
                v += __shfl_xor_sync(0xffffffffu, v, off);
            if (lane == 0) ang[wid * 3 + a] = v + enc_b[a];
        }
    }
    __syncthreads();

    // ---- gate constants ----
    if (tid < P) {
        // colA[w] = RY(q2) RZ(q1) RY(q0) RZ(a2) RY(a1) RX(a0) |0>
        float a0 = ang[tid * 3 + 0], a1 = ang[tid * 3 + 1], a2 = ang[tid * 3 + 2];
        float q0 = qw[tid * 3 + 0], q1 = qw[tid * 3 + 1], q2 = qw[tid * 3 + 2];  // layer 0
        float sA, cA; sincosf(0.5f * a0, &sA, &cA);
        c32 v0 = { cA, 0.f }, v1 = { 0.f, -sA };                 // RX col0
        float sB, cB; sincosf(0.5f * a1, &sB, &cB);              // RY
        c32 t0 = { cB * v0.x - sB * v1.x, cB * v0.y - sB * v1.y };
        c32 t1 = { sB * v0.x + cB * v1.x, sB * v0.y + cB * v1.y };
        float sC, cC; sincosf(0.5f * a2, &sC, &cC);              // RZ
        v0 = cmul({ cC, -sC }, t0); v1 = cmul({ cC, sC }, t1);
        float s0, c0; sincosf(0.5f * q0, &s0, &c0);              // RY
        t0 = { c0 * v0.x - s0 * v1.x, c0 * v0.y - s0 * v1.y };
        t1 = { s0 * v0.x + c0 * v1.x, s0 * v0.y + c0 * v1.y };
        float s1, c1; sincosf(0.5f * q1, &s1, &c1);              // RZ
        v0 = cmul({ c1, -s1 }, t0); v1 = cmul({ c1, s1 }, t1);
        float s2, c2; sincosf(0.5f * q2, &s2, &c2);              // RY
        t0 = { c2 * v0.x - s2 * v1.x, c2 * v0.y - s2 * v1.y };
        t1 = { s2 * v0.x + c2 * v1.x, s2 * v0.y + c2 * v1.y };
        colA[tid * 2 + 0] = t0; colA[tid * 2 + 1] = t1;
    } else if (tid < 2 * P) {
        const int w = tid - P;
        float q0 = qw[(P + w) * 3 + 0], q1 = qw[(P + w) * 3 + 1], q2 = qw[(P + w) * 3 + 2]; // layer 1
        float s0, c0; sincosf(0.5f * q0, &s0, &c0);
        float s1, c1; sincosf(0.5f * q1, &s1, &c1);
        float s2, c2; sincosf(0.5f * q2, &s2, &c2);
        // M1 = RZ(q1)*RY(q0)
        c32 e0 = { c1, -s1 }, e1 = { c1, s1 };
        c32 m00 = {  e0.x * c0,  e0.y * c0 }, m01 = { -e0.x * s0, -e0.y * s0 };
        c32 m10 = {  e1.x * s0,  e1.y * s0 }, m11 = {  e1.x * c0,  e1.y * c0 };
        // U = RY(q2)*M1
        c32 u00 = { c2 * m00.x - s2 * m10.x, c2 * m00.y - s2 * m10.y };
        c32 u01 = { c2 * m01.x - s2 * m11.x, c2 * m01.y - s2 * m11.y };
        c32 u10 = { s2 * m00.x + c2 * m10.x, s2 * m00.y + c2 * m10.y };
        c32 u11 = { s2 * m01.x + c2 * m11.x, s2 * m01.y + c2 * m11.y };
        float* M = matB + w * 8;
        M[0] = u00.x; M[1] = u00.y; M[2] = u01.x; M[3] = u01.y;
        M[4] = u10.x; M[5] = u10.y; M[6] = u11.x; M[7] = u11.y;
    }
    __syncthreads();

    // ---- product-state construction (enc + layer-1 fully collapsed) ----
    {
        // y = 16*tid + j ; y bit (12-w) is wire w.  wires 0..8 <- tid bits 8..0
        c32 pre = colA[0 * 2 + ((tid >> 8) & 1)];
#pragma unroll
        for (int w = 1; w < 9; w++) pre = cmul(pre, colA[w * 2 + ((tid >> (8 - w)) & 1)]);
        c32 q2a[2], q4[4], q8[8];
#pragma unroll
        for (int i = 0; i < 2; i++) q2a[i] = cmul(pre, colA[9 * 2 + i]);
#pragma unroll
        for (int i = 0; i < 4; i++) q4[i] = cmul(q2a[i >> 1], colA[10 * 2 + (i & 1)]);
#pragma unroll
        for (int i = 0; i < 8; i++) q8[i] = cmul(q4[i >> 1], colA[11 * 2 + (i & 1)]);
        const int base = tid << 4;
#pragma unroll
        for (int j = 0; j < 16; j++)
            s[sw(base + j)] = cmul(q8[j >> 1], colA[12 * 2 + (j & 1)]);
    }
    __syncthreads();

    // ---- layer-2 masked gates: 3 register batches of 4 ----
    do_batch<0>(s, matB, tid); __syncthreads();
    do_batch<1>(s, matB, tid); __syncthreads();
    do_batch<2>(s, matB, tid); __syncthreads();

    // ---- final gate (wire 12) fused with measurement ----
    float acc[P];
#pragma unroll
    for (int w = 0; w < P; w++) acc[w] = 0.0f;
    {
        constexpr QCData q = make_qc();
        constexpr int m      = q.m2[12];
        constexpr int r      = q.r2[12];
        constexpr int mlo    = m & (-m);
        constexpr int lomask = mlo - 1;
        const float* M = matB + 12 * 8;
        const c32 u00 = { M[0], M[1] }, u01 = { M[2], M[3] };
        const c32 u10 = { M[4], M[5] }, u11 = { M[6], M[7] };
#pragma unroll
        for (int jj = 0; jj < 8; jj++) {
            const int qi = tid + jj * TPB;                 // 0..4095
            const int x  = ((qi & ~lomask) << 1) | (qi & lomask);
            const int xp = x ^ m;
            c32 va = s[sw(x)], vb = s[sw(xp)];
            const int o = __popc(x & r) & 1;
            c32 a0 = o ? vb : va;
            c32 a1 = o ? va : vb;
            c32 n0 = cadd(cmul(u00, a0), cmul(u01, a1));
            c32 n1 = cadd(cmul(u10, a0), cmul(u11, a1));
            c32 vx = o ? n1 : n0;                          // amp at index x
            c32 vp = o ? n0 : n1;                          // amp at index xp
            float p0 = vx.x * vx.x + vx.y * vx.y;
            float p1 = vp.x * vp.x + vp.y * vp.y;
#pragma unroll
            for (int w = 0; w < P; w++) {
                const int bx = __popc(x & q.rm[w]) & 1;
                acc[w] += bx ? -p0 : p0;
                acc[w] += (bx ^ (cpop(m & q.rm[w]) & 1)) ? -p1 : p1;
            }
        }
    }
#pragma unroll
    for (int w = 0; w < P; w++) {
        float v = acc[w];
#pragma unroll
        for (int off = 16; off; off >>= 1)
            v += __shfl_xor_sync(0xffffffffu, v, off);
        if (lane == 0) wsum[wid * P + w] = v;
    }
    __syncthreads();
    if (tid < P) {
        float v = 0.0f;
        for (int k = 0; k < NWARP; k++) v += wsum[k * P + tid];
        expv[tid] = v;
    }
    __syncthreads();

    // ---- decode + residual ----
    const float al = alpha[0];
    const int base = n * P * D;
    for (int e = tid; e < P * D; e += TPB) {
        const int w = e >> 6;
        const int d = e & 63;
        out[base + e] = h[base + e] + al * expv[w] * dec_w[d];
    }
}

} // anonymous namespace

extern "C" void kernel_launch(void* const* d_in, const int* in_sizes, int n_in,
                              void* d_out, int out_size)
{
    const float* h     = (const float*)d_in[0];
    const float* enc_w = (const float*)d_in[1];
    const float* enc_b = (const float*)d_in[2];
    const float* qw    = (const float*)d_in[3];
    const float* dec_w = (const float*)d_in[4];
    const float* alpha = (const float*)d_in[5];
    float* out = (float*)d_out;

    const int nsamp = in_sizes[0] / (P * D);   // B*T

    cudaFuncSetAttribute(qlc_kernel, cudaFuncAttributeMaxDynamicSharedMemorySize, SMEM_BYTES);
    qlc_kernel<<<nsamp, TPB, SMEM_BYTES>>>(h, enc_w, enc_b, qw, dec_w, alpha, out);
}

// round 9
// speedup vs baseline: 3.6525x; 1.3830x over previous
#include <cuda_runtime.h>
#include <math.h>

namespace {

constexpr int P     = 13;
constexpr int NS    = 1 << P;      // 8192 amplitudes
constexpr int TPB   = 512;
constexpr int D     = 64;
constexpr int NWARP = TPB / 32;

struct c32 { float x, y; };

__device__ __forceinline__ c32 cmul(c32 a, c32 b) {
    return { fmaf(a.x, b.x, -a.y * b.y), fmaf(a.x, b.y, a.y * b.x) };
}
__device__ __forceinline__ c32 cadd(c32 a, c32 b) { return { a.x + b.x, a.y + b.y }; }

// ---------------- compile-time GF(2) machinery ----------------

__host__ __device__ constexpr int cg_cnot(int i, int x) {
    int cb = P - 1 - i;
    int tb = P - 1 - ((i + 1) % P);
    return ((x >> cb) & 1) ? (x ^ (1 << tb)) : x;
}
__host__ __device__ constexpr int cGmap(int y) {
    for (int i = P - 1; i >= 0; --i) y = cg_cnot(i, y);
    return y;
}
__host__ __device__ constexpr int cGinv(int y) {
    for (int i = 0; i < P; i++) y = cg_cnot(i, y);
    return y;
}
__host__ __device__ constexpr int cpop(int x) { int c = 0; for (int i = 0; i < 16; i++) c += (x >> i) & 1; return c; }
__host__ __device__ constexpr int cctz(int x) { for (int i = 0; i < 16; i++) if ((x >> i) & 1) return i; return -1; }

struct QCData {
    int m2[P];            // layer-2 pair masks  G(e_w)
    int r2[P];            // layer-2 orientation masks (rows of G^-1)
    int rm[P];            // measurement parity masks (rows of G^-2)
    int npos[3][9];       // non-pivot bit positions per batch (ascending)
    int combo[3][16];     // XOR offsets of the 16 coset members
    int lm[3][4];         // local 4-bit pair pattern per gate
    int lml[3][4];        // lowest set bit of lm (canonical selector)
    int lr[3][4];         // local parity pattern per gate
    int rw[3][4];         // full orientation mask per gate (for px)
    int odm[8];           // measurement: per-jj orientation delta (compile-time)
    int mg[4];            // measurement: WHT sig generators
    int kw[P];            // measurement: WHT coefficient index per wire
};

__host__ __device__ constexpr QCData make_qc() {
    QCData q{};
    for (int w = 0; w < P; w++) {
        q.m2[w] = cGmap(1 << (P - 1 - w));
        int r = 0, rm = 0;
        for (int p = 0; p < P; p++) {
            int gi  = cGinv(1 << p);
            int gi2 = cGinv(gi);
            r  |= ((gi  >> (P - 1 - w)) & 1) << p;
            rm |= ((gi2 >> (P - 1 - w)) & 1) << p;
        }
        q.r2[w] = r; q.rm[w] = rm;
    }
    for (int b = 0; b < 3; b++) {
        int f[4] = {}, piv[4] = {};
        for (int i = 0; i < 4; i++) f[i] = q.m2[4 * b + i];
        for (int i = 0; i < 4; i++) {
            for (int j = 0; j < i; j++) if ((f[i] >> piv[j]) & 1) f[i] ^= f[j];
            piv[i] = cctz(f[i]);
            for (int j = 0; j < i; j++) if ((f[j] >> piv[i]) & 1) f[j] ^= f[i];
        }
        int np = 0;
        for (int bit = 0; bit < P; bit++) {
            bool isp = false;
            for (int i = 0; i < 4; i++) if (piv[i] == bit) isp = true;
            if (!isp) q.npos[b][np++] = bit;
        }
        for (int j = 0; j < 16; j++) {
            int c = 0;
            for (int i = 0; i < 4; i++) if ((j >> i) & 1) c ^= f[i];
            q.combo[b][j] = c;
        }
        for (int g = 0; g < 4; g++) {
            int m = q.m2[4 * b + g], r = q.r2[4 * b + g];
            int lm = 0, lr = 0;
            for (int i = 0; i < 4; i++) {
                lm |= ((m >> piv[i]) & 1) << i;
                lr |= (cpop(f[i] & r) & 1) << i;
            }
            q.lm[b][g] = lm;
            q.lml[b][g] = lm & (-lm);
            q.lr[b][g] = lr;
            q.rw[b][g] = r;
        }
    }
    // measurement constants (final gate on wire 12 fused with <Z> readout)
    {
        int m12 = q.m2[12], r12 = q.r2[12];
        for (int jj = 0; jj < 8; jj++) q.odm[jj] = cpop((jj << 10) & r12) & 1;
        for (int i = 0; i < 4; i++) {
            int v = (i < 3) ? (1024 << i) : m12;    // idx-bit deltas in amp-index space
            int sgn = 0;
            for (int w = 0; w < P; w++) sgn |= (cpop(v & q.rm[w]) & 1) << w;
            q.mg[i] = sgn;
        }
        for (int w = 0; w < P; w++) {
            int k = 0;
            for (int i = 0; i < 4; i++) k |= ((q.mg[i] >> w) & 1) << i;
            q.kw[w] = k;
        }
    }
    return q;
}

// host-side structural checks only (device code re-materializes its own local constexpr copy)
constexpr QCData QC_HOST = make_qc();
__host__ __device__ constexpr int batch2_support() {
    int s = 0;
    for (int j = 0; j < 16; j++) s |= QC_HOST.combo[2][j];
    return s;
}
static_assert((QC_HOST.m2[12] & 1) == 1, "insert for final gate must be <<1");
static_assert(QC_HOST.npos[2][0] == 4 && QC_HOST.npos[2][8] == 12, "batch2 coset must be low-bit");
static_assert((batch2_support() & ~0x1F) == 0, "batch2 combos must live in bits 0..4");

// SMEM bank-conflict swizzle: XOR bits[7:4] into bits[3:0]. Bijection on [0,8192).
__device__ __forceinline__ int sw(int y) { return y ^ ((y >> 4) & 0xF); }

// ---------------- SMEM layout (floats) ----------------
constexpr int SM_S    = 0;                    // 8192 c32 = 16384 floats
constexpr int SM_ANG  = 16384;                // 13*3 (+pad) = 40
constexpr int SM_COLA = 16424;                // 13*2 c32 = 52 floats (8B aligned)
constexpr int SM_MATB = 16476;                // 13*8 = 104 floats (8B aligned)
constexpr int SM_WSUM = 16580;                // NWARP*13 = 208
constexpr int SM_EXPV = 16788;                // 13
constexpr int SMEM_BYTES = (16788 + 13 + 3) * 4;

// Apply 4 masked gates of batch B to the 16-amp register coset.
// Orientation is folded into two precomputed matrices; inner loop = pure cmuls.
template <int B>
__device__ __forceinline__ void apply_batch_gates(c32* __restrict__ reg,
                                                  const float* __restrict__ matB, int x)
{
    constexpr QCData qc = make_qc();
#pragma unroll
    for (int g = 0; g < 4; g++) {
        const int w = 4 * B + g;
        const float* M = matB + w * 8;
        const c32 u00 = { M[0], M[1] }, u01 = { M[2], M[3] };
        const c32 u10 = { M[4], M[5] }, u11 = { M[6], M[7] };
        const bool px = (__popc(x & qc.rw[B][g]) & 1) != 0;
        // A* = effective stored-basis matrix for pairs with ojc==0, B* for ojc==1
        const c32 A00 = px ? u11 : u00, A01 = px ? u10 : u01;
        const c32 A10 = px ? u01 : u10, A11 = px ? u00 : u11;
        const c32 B00 = px ? u00 : u11, B01 = px ? u01 : u10;
        const c32 B10 = px ? u10 : u01, B11 = px ? u11 : u00;
#pragma unroll
        for (int j = 0; j < 16; j++) {
            if (j & qc.lml[B][g]) continue;                  // canonical of each pair
            const int jp  = j ^ qc.lm[B][g];                 // compile-time partner
            const bool oc = (cpop(j & qc.lr[B][g]) & 1) != 0; // compile-time
            const c32 m00 = oc ? B00 : A00, m01 = oc ? B01 : A01;
            const c32 m10 = oc ? B10 : A10, m11 = oc ? B11 : A11;
            const c32 va = reg[j], vb = reg[jp];
            reg[j]  = cadd(cmul(m00, va), cmul(m01, vb));
            reg[jp] = cadd(cmul(m10, va), cmul(m11, vb));
        }
    }
}

template <int B>
__device__ __forceinline__ void do_batch(c32* __restrict__ s,
                                         const float* __restrict__ matB, int tid)
{
    constexpr QCData qc = make_qc();
    int x = 0;
#pragma unroll
    for (int i = 0; i < 9; i++) x |= ((tid >> i) & 1) << qc.npos[B][i];

    c32 reg[16];
#pragma unroll
    for (int j = 0; j < 16; j++) reg[j] = s[sw(x ^ qc.combo[B][j])];

    apply_batch_gates<B>(reg, matB, x);

#pragma unroll
    for (int j = 0; j < 16; j++) s[sw(x ^ qc.combo[B][j])] = reg[j];
}

__global__ void __launch_bounds__(TPB, 2)
qlc_kernel(const float* __restrict__ h,
           const float* __restrict__ enc_w,
           const float* __restrict__ enc_b,
           const float* __restrict__ qw,
           const float* __restrict__ dec_w,
           const float* __restrict__ alpha,
           float* __restrict__ out)
{
    extern __shared__ float smemf[];
    c32*   s    = (c32*)(smemf + SM_S);
    float* ang  = smemf + SM_ANG;
    c32*   colA = (c32*)(smemf + SM_COLA);   // [13][2] fused (enc+L1) column-0
    float* matB = smemf + SM_MATB;           // [13][8] layer-2 gate matrices
    float* wsum = smemf + SM_WSUM;
    float* expv = smemf + SM_EXPV;

    const int n = blockIdx.x, tid = threadIdx.x, wid = tid >> 5, lane = tid & 31;

    // ---- encoding angles: one warp per wire ----
    if (wid < P) {
        const float* hrow = h + (n * P + wid) * D;
        float h0 = hrow[lane], h1 = hrow[lane + 32];
#pragma unroll
        for (int a = 0; a < 3; a++) {
            float v = h0 * enc_w[a * D + lane] + h1 * enc_w[a * D + lane + 32];
#pragma unroll
            for (int off = 16; off; off >>= 1)
                v += __shfl_xor_sync(0xffffffffu, v, off);
            if (lane == 0) ang[wid * 3 + a] = v + enc_b[a];
        }
    }
    __syncthreads();

    // ---- gate constants ----
    if (tid < P) {
        // colA[w] = RY(q2) RZ(q1) RY(q0) RZ(a2) RY(a1) RX(a0) |0>
        float a0 = ang[tid * 3 + 0], a1 = ang[tid * 3 + 1], a2 = ang[tid * 3 + 2];
        float q0 = qw[tid * 3 + 0], q1 = qw[tid * 3 + 1], q2 = qw[tid * 3 + 2];  // layer 0
        float sA, cA; sincosf(0.5f * a0, &sA, &cA);
        c32 v0 = { cA, 0.f }, v1 = { 0.f, -sA };                 // RX col0
        float sB, cB; sincosf(0.5f * a1, &sB, &cB);              // RY
        c32 t0 = { cB * v0.x - sB * v1.x, cB * v0.y - sB * v1.y };
        c32 t1 = { sB * v0.x + cB * v1.x, sB * v0.y + cB * v1.y };
        float sC, cC; sincosf(0.5f * a2, &sC, &cC);              // RZ
        v0 = cmul({ cC, -sC }, t0); v1 = cmul({ cC, sC }, t1);
        float s0, c0; sincosf(0.5f * q0, &s0, &c0);              // RY
        t0 = { c0 * v0.x - s0 * v1.x, c0 * v0.y - s0 * v1.y };
        t1 = { s0 * v0.x + c0 * v1.x, s0 * v0.y + c0 * v1.y };
        float s1, c1; sincosf(0.5f * q1, &s1, &c1);              // RZ
        v0 = cmul({ c1, -s1 }, t0); v1 = cmul({ c1, s1 }, t1);
        float s2, c2; sincosf(0.5f * q2, &s2, &c2);              // RY
        t0 = { c2 * v0.x - s2 * v1.x, c2 * v0.y - s2 * v1.y };
        t1 = { s2 * v0.x + c2 * v1.x, s2 * v0.y + c2 * v1.y };
        colA[tid * 2 + 0] = t0; colA[tid * 2 + 1] = t1;
    } else if (tid < 2 * P) {
        const int w = tid - P;
        float q0 = qw[(P + w) * 3 + 0], q1 = qw[(P + w) * 3 + 1], q2 = qw[(P + w) * 3 + 2]; // layer 1
        float s0, c0; sincosf(0.5f * q0, &s0, &c0);
        float s1, c1; sincosf(0.5f * q1, &s1, &c1);
        float s2, c2; sincosf(0.5f * q2, &s2, &c2);
        // M1 = RZ(q1)*RY(q0)
        c32 e0 = { c1, -s1 }, e1 = { c1, s1 };
        c32 m00 = {  e0.x * c0,  e0.y * c0 }, m01 = { -e0.x * s0, -e0.y * s0 };
        c32 m10 = {  e1.x * s0,  e1.y * s0 }, m11 = {  e1.x * c0,  e1.y * c0 };
        // U = RY(q2)*M1
        c32 u00 = { c2 * m00.x - s2 * m10.x, c2 * m00.y - s2 * m10.y };
        c32 u01 = { c2 * m01.x - s2 * m11.x, c2 * m01.y - s2 * m11.y };
        c32 u10 = { s2 * m00.x + c2 * m10.x, s2 * m00.y + c2 * m10.y };
        c32 u11 = { s2 * m01.x + c2 * m11.x, s2 * m01.y + c2 * m11.y };
        float* M = matB + w * 8;
        M[0] = u00.x; M[1] = u00.y; M[2] = u01.x; M[3] = u01.y;
        M[4] = u10.x; M[5] = u10.y; M[6] = u11.x; M[7] = u11.y;
    }
    __syncthreads();

    // ---- product-state construction FUSED with batch-2 gates (registers only) ----
    {
        constexpr QCData qc = make_qc();
        // x = tid<<4 (batch-2 coset representative; static_asserted structure).
        // Common prefix over wires 0..7 (bits 12..5):
        c32 pre = colA[0 * 2 + ((tid >> 8) & 1)];
#pragma unroll
        for (int w = 1; w < 8; w++) pre = cmul(pre, colA[w * 2 + ((tid >> (8 - w)) & 1)]);
        // wires 8,9 (bits 4,3), with pre folded in:
        c32 ph[4];
#pragma unroll
        for (int t = 0; t < 4; t++)
            ph[t] = cmul(pre, cmul(colA[8 * 2 + (t >> 1)], colA[9 * 2 + (t & 1)]));
        const int t0b = tid & 1;                  // runtime bit 4 of x
        c32 phe[4];
#pragma unroll
        for (int t = 0; t < 4; t++) phe[t] = t0b ? ph[t ^ 2] : ph[t];
        // wires 10,11,12 (bits 2,1,0):
        c32 t2[4];
#pragma unroll
        for (int t = 0; t < 4; t++) t2[t] = cmul(colA[10 * 2 + (t >> 1)], colA[11 * 2 + (t & 1)]);
        c32 pl[8];
#pragma unroll
        for (int u = 0; u < 8; u++) pl[u] = cmul(t2[u >> 1], colA[12 * 2 + (u & 1)]);

        c32 reg[16];
#pragma unroll
        for (int j = 0; j < 16; j++) {
            const int cj = qc.combo[2][j];
            reg[j] = cmul(phe[(cj >> 3) & 3], pl[cj & 7]);
        }
        const int x = tid << 4;
        apply_batch_gates<2>(reg, matB, x);
#pragma unroll
        for (int j = 0; j < 16; j++) s[sw(x ^ qc.combo[2][j])] = reg[j];
    }
    __syncthreads();

    // ---- remaining layer-2 gate batches ----
    do_batch<0>(s, matB, tid); __syncthreads();
    do_batch<1>(s, matB, tid); __syncthreads();

    // ---- final gate (wire 12) fused with <Z_w> via compile-time WHT signs ----
    {
        constexpr QCData qc = make_qc();
        constexpr int m12 = qc.m2[12];
        constexpr int r12 = qc.r2[12];
        const float* M = matB + 12 * 8;
        const c32 u00 = { M[0], M[1] }, u01 = { M[2], M[3] };
        const c32 u10 = { M[4], M[5] }, u11 = { M[6], M[7] };
        const int  x0 = tid << 1;                 // insert(tid), lomask==0
        const bool o0 = (__popc(x0 & r12) & 1) != 0;
        const c32 A00 = o0 ? u11 : u00, A01 = o0 ? u10 : u01;
        const c32 A10 = o0 ? u01 : u10, A11 = o0 ? u00 : u11;
        const c32 B00 = o0 ? u00 : u11, B01 = o0 ? u01 : u10;
        const c32 B10 = o0 ? u10 : u01, B11 = o0 ? u11 : u00;

        float p[16];
#pragma unroll
        for (int jj = 0; jj < 8; jj++) {
            const int x  = x0 ^ (jj << 10);
            const int xp = x ^ m12;
            const c32 va = s[sw(x)], vb = s[sw(xp)];
            const bool od = qc.odm[jj] != 0;       // compile-time
            const c32 m00 = od ? B00 : A00, m01 = od ? B01 : A01;
            const c32 m10 = od ? B10 : A10, m11 = od ? B11 : A11;
            const c32 n0 = cadd(cmul(m00, va), cmul(m01, vb));
            const c32 n1 = cadd(cmul(m10, va), cmul(m11, vb));
            p[jj]     = fmaf(n0.x, n0.x, n0.y * n0.y);   // prob at index x
            p[jj | 8] = fmaf(n1.x, n1.x, n1.y * n1.y);   // prob at index x^m
        }
        // 16-point Walsh–Hadamard (all signs compile-time)
#pragma unroll
        for (int st = 1; st < 16; st <<= 1) {
#pragma unroll
            for (int k = 0; k < 16; k++)
                if (!(k & st)) {
                    const float a = p[k], b = p[k ^ st];
                    p[k] = a + b; p[k ^ st] = a - b;
                }
        }
        int sig0 = 0;
#pragma unroll
        for (int w = 0; w < P; w++) sig0 |= (__popc(x0 & qc.rm[w]) & 1) << w;
#pragma unroll
        for (int w = 0; w < P; w++) {
            float v = p[qc.kw[w]];
            v = ((sig0 >> w) & 1) ? -v : v;
#pragma unroll
            for (int off = 16; off; off >>= 1)
                v += __shfl_xor_sync(0xffffffffu, v, off);
            if (lane == 0) wsum[wid * P + w] = v;
        }
    }
    __syncthreads();
    if (tid < P) {
        float v = 0.0f;
        for (int k = 0; k < NWARP; k++) v += wsum[k * P + tid];
        expv[tid] = v;
    }
    __syncthreads();

    // ---- decode + residual ----
    const float al = alpha[0];
    const int base = n * P * D;
    for (int e = tid; e < P * D; e += TPB) {
        const int w = e >> 6;
        const int d = e & 63;
        out[base + e] = h[base + e] + al * expv[w] * dec_w[d];
    }
}

} // anonymous namespace

extern "C" void kernel_launch(void* const* d_in, const int* in_sizes, int n_in,
                              void* d_out, int out_size)
{
    const float* h     = (const float*)d_in[0];
    const float* enc_w = (const float*)d_in[1];
    const float* enc_b = (const float*)d_in[2];
    const float* qw    = (const float*)d_in[3];
    const float* dec_w = (const float*)d_in[4];
    const float* alpha = (const float*)d_in[5];
    float* out = (float*)d_out;

    const int nsamp = in_sizes[0] / (P * D);   // B*T

    cudaFuncSetAttribute(qlc_kernel, cudaFuncAttributeMaxDynamicSharedMemorySize, SMEM_BYTES);
    qlc_kernel<<<nsamp, TPB, SMEM_BYTES>>>(h, enc_w, enc_b, qw, dec_w, alpha, out);
}

// round 12
// speedup vs baseline: 3.9253x; 1.0747x over previous
#include <cuda_runtime.h>
#include <math.h>

namespace {

constexpr int P     = 13;
constexpr int NS    = 1 << P;      // 8192 amplitudes
constexpr int TPB   = 512;
constexpr int D     = 64;
constexpr int NWARP = TPB / 32;

struct c32 { float x, y; };
typedef unsigned long long u64;

__device__ __forceinline__ c32 cmul(c32 a, c32 b) {
    return { fmaf(a.x, b.x, -a.y * b.y), fmaf(a.x, b.y, a.y * b.x) };
}

// ---------------- packed f32x2 helpers ----------------
__device__ __forceinline__ u64 pk2(float x, float y) {
    u64 r; asm("mov.b64 %0, {%1, %2};" : "=l"(r) : "f"(x), "f"(y)); return r;
}
__device__ __forceinline__ void upk2(u64 v, float& x, float& y) {
    asm("mov.b64 {%0, %1}, %2;" : "=f"(x), "=f"(y) : "l"(v));
}
__device__ __forceinline__ u64 swp2(u64 v) {
    u64 r;
    asm("{ .reg .b32 lo, hi; mov.b64 {lo, hi}, %1; mov.b64 %0, {hi, lo}; }"
        : "=l"(r) : "l"(v));
    return r;
}
__device__ __forceinline__ u64 mul2(u64 a, u64 b) {
    u64 r; asm("mul.rn.f32x2 %0, %1, %2;" : "=l"(r) : "l"(a), "l"(b)); return r;
}
__device__ __forceinline__ u64 fma2(u64 a, u64 b, u64 c) {
    u64 r; asm("fma.rn.f32x2 %0, %1, %2, %3;" : "=l"(r) : "l"(a), "l"(b), "l"(c)); return r;
}
__device__ __forceinline__ u64 splat_xx(c32 m) {
    u64 r; asm("mov.b64 %0, {%1, %1};" : "=l"(r) : "f"(m.x)); return r;
}
__device__ __forceinline__ u64 splat_yn(c32 m) {
    u64 r; asm("mov.b64 %0, {%1, %2};" : "=l"(r) : "f"(-m.y), "f"(m.y)); return r;
}
// n = m0*va + m1*vb  (complex, packed):  va,vb packed {x,y}; vas,vbs their swaps {y,x}
__device__ __forceinline__ u64 bfly(u64 va, u64 vas, u64 vb, u64 vbs,
                                    u64 m0xx, u64 m0yn, u64 m1xx, u64 m1yn) {
    return fma2(va, m0xx, fma2(vas, m0yn, fma2(vb, m1xx, mul2(vbs, m1yn))));
}

// ---------------- compile-time GF(2) machinery ----------------

__host__ __device__ constexpr int cg_cnot(int i, int x) {
    int cb = P - 1 - i;
    int tb = P - 1 - ((i + 1) % P);
    return ((x >> cb) & 1) ? (x ^ (1 << tb)) : x;
}
__host__ __device__ constexpr int cGmap(int y) {
    for (int i = P - 1; i >= 0; --i) y = cg_cnot(i, y);
    return y;
}
__host__ __device__ constexpr int cGinv(int y) {
    for (int i = 0; i < P; i++) y = cg_cnot(i, y);
    return y;
}
__host__ __device__ constexpr int cpop(int x) { int c = 0; for (int i = 0; i < 16; i++) c += (x >> i) & 1; return c; }
__host__ __device__ constexpr int cctz(int x) { for (int i = 0; i < 16; i++) if ((x >> i) & 1) return i; return -1; }

struct QCData {
    int m2[P];            // layer-2 pair masks  G(e_w)
    int r2[P];            // layer-2 orientation masks (rows of G^-1)
    int rm[P];            // measurement parity masks (rows of G^-2)
    int npos[3][9];       // non-pivot bit positions per batch (ascending)
    int combo[3][16];     // XOR offsets of the 16 coset members
    int lm[3][4];         // local 4-bit pair pattern per gate
    int lml[3][4];        // lowest set bit of lm (canonical selector)
    int lr[3][4];         // local parity pattern per gate
    int rw[3][4];         // full orientation mask per gate (for px)
    int odm[8];           // measurement: per-jj orientation delta (compile-time)
    int mg[4];            // measurement: WHT sig generators
    int kw[P];            // measurement: WHT coefficient index per wire
};

__host__ __device__ constexpr QCData make_qc() {
    QCData q{};
    for (int w = 0; w < P; w++) {
        q.m2[w] = cGmap(1 << (P - 1 - w));
        int r = 0, rm = 0;
        for (int p = 0; p < P; p++) {
            int gi  = cGinv(1 << p);
            int gi2 = cGinv(gi);
            r  |= ((gi  >> (P - 1 - w)) & 1) << p;
            rm |= ((gi2 >> (P - 1 - w)) & 1) << p;
        }
        q.r2[w] = r; q.rm[w] = rm;
    }
    for (int b = 0; b < 3; b++) {
        int f[4] = {}, piv[4] = {};
        for (int i = 0; i < 4; i++) f[i] = q.m2[4 * b + i];
        for (int i = 0; i < 4; i++) {
            for (int j = 0; j < i; j++) if ((f[i] >> piv[j]) & 1) f[i] ^= f[j];
            piv[i] = cctz(f[i]);
            for (int j = 0; j < i; j++) if ((f[j] >> piv[i]) & 1) f[j] ^= f[i];
        }
        int np = 0;
        for (int bit = 0; bit < P; bit++) {
            bool isp = false;
            for (int i = 0; i < 4; i++) if (piv[i] == bit) isp = true;
            if (!isp) q.npos[b][np++] = bit;
        }
        for (int j = 0; j < 16; j++) {
            int c = 0;
            for (int i = 0; i < 4; i++) if ((j >> i) & 1) c ^= f[i];
            q.combo[b][j] = c;
        }
        for (int g = 0; g < 4; g++) {
            int m = q.m2[4 * b + g], r = q.r2[4 * b + g];
            int lm = 0, lr = 0;
            for (int i = 0; i < 4; i++) {
                lm |= ((m >> piv[i]) & 1) << i;
                lr |= (cpop(f[i] & r) & 1) << i;
            }
            q.lm[b][g] = lm;
            q.lml[b][g] = lm & (-lm);
            q.lr[b][g] = lr;
            q.rw[b][g] = r;
        }
    }
    // measurement constants (final gate on wire 12 fused with <Z> readout)
    {
        int m12 = q.m2[12], r12 = q.r2[12];
        for (int jj = 0; jj < 8; jj++) q.odm[jj] = cpop((jj << 10) & r12) & 1;
        for (int i = 0; i < 4; i++) {
            int v = (i < 3) ? (1024 << i) : m12;    // idx-bit deltas in amp-index space
            int sgn = 0;
            for (int w = 0; w < P; w++) sgn |= (cpop(v & q.rm[w]) & 1) << w;
            q.mg[i] = sgn;
        }
        for (int w = 0; w < P; w++) {
            int k = 0;
            for (int i = 0; i < 4; i++) k |= ((q.mg[i] >> w) & 1) << i;
            q.kw[w] = k;
        }
    }
    return q;
}

// host-side structural checks only (device code re-materializes its own local constexpr copy)
constexpr QCData QC_HOST = make_qc();
__host__ __device__ constexpr int batch2_support() {
    int s = 0;
    for (int j = 0; j < 16; j++) s |= QC_HOST.combo[2][j];
    return s;
}
static_assert((QC_HOST.m2[12] & 1) == 1, "insert for final gate must be <<1");
static_assert(QC_HOST.npos[2][0] == 4 && QC_HOST.npos[2][8] == 12, "batch2 coset must be low-bit");
static_assert((batch2_support() & ~0x1F) == 0, "batch2 combos must live in bits 0..4");

// SMEM bank-conflict swizzle: XOR bits[7:4] into bits[3:0]. Bijection on [0,8192).
__device__ __forceinline__ int sw(int y) { return y ^ ((y >> 4) & 0xF); }

// ---------------- SMEM layout (floats) ----------------
constexpr int SM_S    = 0;                    // 8192 c32 = 16384 floats
constexpr int SM_ANG  = 16384;                // 13*3 (+pad) = 40
constexpr int SM_COLA = 16424;                // 13*2 c32 = 52 floats (8B aligned)
constexpr int SM_MATB = 16476;                // 13*8 = 104 floats (8B aligned)
constexpr int SM_WSUM = 16580;                // NWARP*13 = 208
constexpr int SM_EXPV = 16788;                // 13
constexpr int SMEM_BYTES = (16788 + 13 + 3) * 4;

// Apply 4 masked gates of batch B to the 16-amp packed register coset.
// Orientation: px selects the effective element tuple E (runtime, hoisted per
// gate); oc (compile-time per pair) reverses the tuple: (E00,E01,E10,E11) ->
// (E11,E10,E01,E00). Inner loop is pure packed f32x2 FMA chains.
template <int B>
__device__ __forceinline__ void apply_batch_gates(u64* __restrict__ reg,
                                                  const float* __restrict__ matB, int x)
{
    constexpr QCData qc = make_qc();
#pragma unroll
    for (int g = 0; g < 4; g++) {
        const int w = 4 * B + g;
        const float* M = matB + w * 8;
        const c32 u00 = { M[0], M[1] }, u01 = { M[2], M[3] };
        const c32 u10 = { M[4], M[5] }, u11 = { M[6], M[7] };
        const bool px = (__popc(x & qc.rw[B][g]) & 1) != 0;
        const c32 e00 = px ? u11 : u00, e01 = px ? u10 : u01;
        const c32 e10 = px ? u01 : u10, e11 = px ? u00 : u11;
        const u64 E0xx = splat_xx(e00), E0yn = splat_yn(e00);
        const u64 E1xx = splat_xx(e01), E1yn = splat_yn(e01);
        const u64 E2xx = splat_xx(e10), E2yn = splat_yn(e10);
        const u64 E3xx = splat_xx(e11), E3yn = splat_yn(e11);
#pragma unroll
        for (int j = 0; j < 16; j++) {
            if (j & qc.lml[B][g]) continue;                  // canonical of each pair
            const int jp  = j ^ qc.lm[B][g];                 // compile-time partner
            const bool oc = (cpop(j & qc.lr[B][g]) & 1) != 0; // compile-time
            const u64 m00xx = oc ? E3xx : E0xx, m00yn = oc ? E3yn : E0yn;
            const u64 m01xx = oc ? E2xx : E1xx, m01yn = oc ? E2yn : E1yn;
            const u64 m10xx = oc ? E1xx : E2xx, m10yn = oc ? E1yn : E2yn;
            const u64 m11xx = oc ? E0xx : E3xx, m11yn = oc ? E0yn : E3yn;
            const u64 va = reg[j], vb = reg[jp];
            const u64 vas = swp2(va), vbs = swp2(vb);
            reg[j]  = bfly(va, vas, vb, vbs, m00xx, m00yn, m01xx, m01yn);
            reg[jp] = bfly(va, vas, vb, vbs, m10xx, m10yn, m11xx, m11yn);
        }
    }
}

template <int B>
__device__ __forceinline__ void do_batch(u64* __restrict__ s64,
                                         const float* __restrict__ matB, int tid)
{
    constexpr QCData qc = make_qc();
    int x = 0;
#pragma unroll
    for (int i = 0; i < 9; i++) x |= ((tid >> i) & 1) << qc.npos[B][i];

    u64 reg[16];
#pragma unroll
    for (int j = 0; j < 16; j++) reg[j] = s64[sw(x ^ qc.combo[B][j])];

    apply_batch_gates<B>(reg, matB, x);

#pragma unroll
    for (int j = 0; j < 16; j++) s64[sw(x ^ qc.combo[B][j])] = reg[j];
}

__global__ void __launch_bounds__(TPB, 2)
qlc_kernel(const float* __restrict__ h,
           const float* __restrict__ enc_w,
           const float* __restrict__ enc_b,
           const float* __restrict__ qw,
           const float* __restrict__ dec_w,
           const float* __restrict__ alpha,
           float* __restrict__ out)
{
    extern __shared__ float smemf[];
    u64*   s64  = (u64*)(smemf + SM_S);
    float* ang  = smemf + SM_ANG;
    c32*   colA = (c32*)(smemf + SM_COLA);   // [13][2] fused (enc+L1) column-0
    float* matB = smemf + SM_MATB;           // [13][8] layer-2 gate matrices
    float* wsum = smemf + SM_WSUM;
    float* expv = smemf + SM_EXPV;

    const int n = blockIdx.x, tid = threadIdx.x, wid = tid >> 5, lane = tid & 31;

    // ---- encoding angles: one warp per wire ----
    if (wid < P) {
        const float* hrow = h + (n * P + wid) * D;
        float h0 = hrow[lane], h1 = hrow[lane + 32];
#pragma unroll
        for (int a = 0; a < 3; a++) {
            float v = h0 * enc_w[a * D + lane] + h1 * enc_w[a * D + lane + 32];
#pragma unroll
            for (int off = 16; off; off >>= 1)
                v += __shfl_xor_sync(0xffffffffu, v, off);
            if (lane == 0) ang[wid * 3 + a] = v + enc_b[a];
        }
    }
    __syncthreads();

    // ---- gate constants ----
    if (tid < P) {
        // colA[w] = RY(q2) RZ(q1) RY(q0) RZ(a2) RY(a1) RX(a0) |0>
        float a0 = ang[tid * 3 + 0], a1 = ang[tid * 3 + 1], a2 = ang[tid * 3 + 2];
        float q0 = qw[tid * 3 + 0], q1 = qw[tid * 3 + 1], q2 = qw[tid * 3 + 2];  // layer 0
        float sA, cA; sincosf(0.5f * a0, &sA, &cA);
        c32 v0 = { cA, 0.f }, v1 = { 0.f, -sA };                 // RX col0
        float sB, cB; sincosf(0.5f * a1, &sB, &cB);              // RY
        c32 t0 = { cB * v0.x - sB * v1.x, cB * v0.y - sB * v1.y };
        c32 t1 = { sB * v0.x + cB * v1.x, sB * v0.y + cB * v1.y };
        float sC, cC; sincosf(0.5f * a2, &sC, &cC);              // RZ
        v0 = cmul({ cC, -sC }, t0); v1 = cmul({ cC, sC }, t1);
        float s0, c0; sincosf(0.5f * q0, &s0, &c0);              // RY
        t0 = { c0 * v0.x - s0 * v1.x, c0 * v0.y - s0 * v1.y };
        t1 = { s0 * v0.x + c0 * v1.x, s0 * v0.y + c0 * v1.y };
        float s1, c1; sincosf(0.5f * q1, &s1, &c1);              // RZ
        v0 = cmul({ c1, -s1 }, t0); v1 = cmul({ c1, s1 }, t1);
        float s2, c2; sincosf(0.5f * q2, &s2, &c2);              // RY
        t0 = { c2 * v0.x - s2 * v1.x, c2 * v0.y - s2 * v1.y };
        t1 = { s2 * v0.x + c2 * v1.x, s2 * v0.y + c2 * v1.y };
        colA[tid * 2 + 0] = t0; colA[tid * 2 + 1] = t1;
    } else if (tid < 2 * P) {
        const int w = tid - P;
        float q0 = qw[(P + w) * 3 + 0], q1 = qw[(P + w) * 3 + 1], q2 = qw[(P + w) * 3 + 2]; // layer 1
        float s0, c0; sincosf(0.5f * q0, &s0, &c0);
        float s1, c1; sincosf(0.5f * q1, &s1, &c1);
        float s2, c2; sincosf(0.5f * q2, &s2, &c2);
        // M1 = RZ(q1)*RY(q0)
        c32 e0 = { c1, -s1 }, e1 = { c1, s1 };
        c32 m00 = {  e0.x * c0,  e0.y * c0 }, m01 = { -e0.x * s0, -e0.y * s0 };
        c32 m10 = {  e1.x * s0,  e1.y * s0 }, m11 = {  e1.x * c0,  e1.y * c0 };
        // U = RY(q2)*M1
        c32 u00 = { c2 * m00.x - s2 * m10.x, c2 * m00.y - s2 * m10.y };
        c32 u01 = { c2 * m01.x - s2 * m11.x, c2 * m01.y - s2 * m11.y };
        c32 u10 = { s2 * m00.x + c2 * m10.x, s2 * m00.y + c2 * m10.y };
        c32 u11 = { s2 * m01.x + c2 * m11.x, s2 * m01.y + c2 * m11.y };
        float* M = matB + w * 8;
        M[0] = u00.x; M[1] = u00.y; M[2] = u01.x; M[3] = u01.y;
        M[4] = u10.x; M[5] = u10.y; M[6] = u11.x; M[7] = u11.y;
    }
    __syncthreads();

    // ---- product-state construction FUSED with batch-2 gates (registers only) ----
    {
        constexpr QCData qc = make_qc();
        // x = tid<<4 (batch-2 coset representative; static_asserted structure).
        // Common prefix over wires 0..7 (bits 12..5):
        c32 pre = colA[0 * 2 + ((tid >> 8) & 1)];
#pragma unroll
        for (int w = 1; w < 8; w++) pre = cmul(pre, colA[w * 2 + ((tid >> (8 - w)) & 1)]);
        // wires 8,9 (bits 4,3), with pre folded in:
        c32 ph[4];
#pragma unroll
        for (int t = 0; t < 4; t++)
            ph[t] = cmul(pre, cmul(colA[8 * 2 + (t >> 1)], colA[9 * 2 + (t & 1)]));
        const int t0b = tid & 1;                  // runtime bit 4 of x
        c32 phe[4];
#pragma unroll
        for (int t = 0; t < 4; t++) phe[t] = t0b ? ph[t ^ 2] : ph[t];
        // wires 10,11,12 (bits 2,1,0):
        c32 t2[4];
#pragma unroll
        for (int t = 0; t < 4; t++) t2[t] = cmul(colA[10 * 2 + (t >> 1)], colA[11 * 2 + (t & 1)]);
        c32 pl[8];
#pragma unroll
        for (int u = 0; u < 8; u++) pl[u] = cmul(t2[u >> 1], colA[12 * 2 + (u & 1)]);

        u64 reg[16];
#pragma unroll
        for (int j = 0; j < 16; j++) {
            const int cj = qc.combo[2][j];
            const c32 v = cmul(phe[(cj >> 3) & 3], pl[cj & 7]);
            reg[j] = pk2(v.x, v.y);
        }
        const int x = tid << 4;
        apply_batch_gates<2>(reg, matB, x);
#pragma unroll
        for (int j = 0; j < 16; j++) s64[sw(x ^ qc.combo[2][j])] = reg[j];
    }
    __syncthreads();

    // ---- remaining layer-2 gate batches ----
    do_batch<0>(s64, matB, tid); __syncthreads();
    do_batch<1>(s64, matB, tid); __syncthreads();

    // ---- final gate (wire 12) fused with <Z_w> via compile-time WHT signs ----
    {
        constexpr QCData qc = make_qc();
        constexpr int m12 = qc.m2[12];
        constexpr int r12 = qc.r2[12];
        const float* M = matB + 12 * 8;
        const c32 u00 = { M[0], M[1] }, u01 = { M[2], M[3] };
        const c32 u10 = { M[4], M[5] }, u11 = { M[6], M[7] };
        const int  x0 = tid << 1;                 // insert(tid), lomask==0
        const bool o0 = (__popc(x0 & r12) & 1) != 0;
        const c32 e00 = o0 ? u11 : u00, e01 = o0 ? u10 : u01;
        const c32 e10 = o0 ? u01 : u10, e11 = o0 ? u00 : u11;
        const u64 E0xx = splat_xx(e00), E0yn = splat_yn(e00);
        const u64 E1xx = splat_xx(e01), E1yn = splat_yn(e01);
        const u64 E2xx = splat_xx(e10), E2yn = splat_yn(e10);
        const u64 E3xx = splat_xx(e11), E3yn = splat_yn(e11);

        float p[16];
#pragma unroll
        for (int jj = 0; jj < 8; jj++) {
            const int x  = x0 ^ (jj << 10);
            const int xp = x ^ m12;
            const u64 va = s64[sw(x)], vb = s64[sw(xp)];
            const u64 vas = swp2(va), vbs = swp2(vb);
            const bool od = qc.odm[jj] != 0;       // compile-time
            const u64 m00xx = od ? E3xx : E0xx, m00yn = od ? E3yn : E0yn;
            const u64 m01xx = od ? E2xx : E1xx, m01yn = od ? E2yn : E1yn;
            const u64 m10xx = od ? E1xx : E2xx, m10yn = od ? E1yn : E2yn;
            const u64 m11xx = od ? E0xx : E3xx, m11yn = od ? E0yn : E3yn;
            const u64 n0 = bfly(va, vas, vb, vbs, m00xx, m00yn, m01xx, m01yn);
            const u64 n1 = bfly(va, vas, vb, vbs, m10xx, m10yn, m11xx, m11yn);
            float n0x, n0y, n1x, n1y;
            upk2(n0, n0x, n0y); upk2(n1, n1x, n1y);
            p[jj]     = fmaf(n0x, n0x, n0y * n0y);   // prob at index x
            p[jj | 8] = fmaf(n1x, n1x, n1y * n1y);   // prob at index x^m
        }
        // 16-point Walsh–Hadamard (all signs compile-time)
#pragma unroll
        for (int st = 1; st < 16; st <<= 1) {
#pragma unroll
            for (int k = 0; k < 16; k++)
                if (!(k & st)) {
                    const float a = p[k], b = p[k ^ st];
                    p[k] = a + b; p[k ^ st] = a - b;
                }
        }
        int sig0 = 0;
#pragma unroll
        for (int w = 0; w < P; w++) sig0 |= (__popc(x0 & qc.rm[w]) & 1) << w;
#pragma unroll
        for (int w = 0; w < P; w++) {
            float v = p[qc.kw[w]];
            v = ((sig0 >> w) & 1) ? -v : v;
#pragma unroll
            for (int off = 16; off; off >>= 1)
                v += __shfl_xor_sync(0xffffffffu, v, off);
            if (lane == 0) wsum[wid * P + w] = v;
        }
    }
    __syncthreads();
    if (tid < P) {
        float v = 0.0f;
        for (int k = 0; k < NWARP; k++) v += wsum[k * P + tid];
        expv[tid] = v;
    }
    __syncthreads();

    // ---- decode + residual ----
    const float al = alpha[0];
    const int base = n * P * D;
    for (int e = tid; e < P * D; e += TPB) {
        const int w = e >> 6;
        const int d = e & 63;
        out[base + e] = h[base + e] + al * expv[w] * dec_w[d];
    }
}

} // anonymous namespace

extern "C" void kernel_launch(void* const* d_in, const int* in_sizes, int n_in,
                              void* d_out, int out_size)
{
    const float* h     = (const float*)d_in[0];
    const float* enc_w = (const float*)d_in[1];
    const float* enc_b = (const float*)d_in[2];
    const float* qw    = (const float*)d_in[3];
    const float* dec_w = (const float*)d_in[4];
    const float* alpha = (const float*)d_in[5];
    float* out = (float*)d_out;

    const int nsamp = in_sizes[0] / (P * D);   // B*T

    cudaFuncSetAttribute(qlc_kernel, cudaFuncAttributeMaxDynamicSharedMemorySize, SMEM_BYTES);
    qlc_kernel<<<nsamp, TPB, SMEM_BYTES>>>(h, enc_w, enc_b, qw, dec_w, alpha, out);
}